// round 5
// baseline (speedup 1.0000x reference)
#include <cuda_runtime.h>
#include <math.h>

#define THRESH 1e-4f
#define MAXBP  8192
#define BIGL   0x40000000

// ---- kA config ----
#define BLKA 128
#define CHA  45                     // odd stride -> conflict-free smem chain reads
#define WUP  40
#define TILE (BLKA*CHA)             // 5760
#define XN   (TILE + WUP + 32)      // staged cc: t in [B-WUP, B+TILE+31]
#define SZN  (TILE + 32)
// static smem: (XN + SZN + 4)*4 = 46512 B < 48 KB static cap
// box-screen constants: TH^(1/6)*0.997 and TH^(1/5)*1.02
#define C6BOX 0.212742f
#define C5BOX 0.161659f

// ---- k4 config ----
#define BLKB  256
#define HALOB 8

// Scratch (no allocations); zero-init first run, self-reset for graph replays.
__device__ int g_anom_n = 0;
__device__ int g_ticket = 0;
__device__ int g_anom_p[MAXBP];
__device__ int g_anom_l[MAXBP];
__device__ int g_K;
__device__ int g_P[MAXBP];
__device__ int g_Q[MAXBP];
__device__ float g_C[8];            // w2, w4_2, dt1, dt2, d2t1, d2t2

// ============================================================================
// kA: fused Z-scan + box-screened anomaly scan + orbit walk (+ consts export).
// ============================================================================
__global__ __launch_bounds__(BLKA) void kA(const float* __restrict__ X,
                                           const float* __restrict__ pr,
                                           float* __restrict__ Z, int T) {
    __shared__ float sCC[XN];
    __shared__ float sZ[SZN];
    __shared__ float sC[4];         // w1,w2,w3,w4 (post-tanh)
    int nsteps = T - 1;
    int B = blockIdx.x * TILE;
    int tid = threadIdx.x;

    if (tid == 0) {                 // tanh(double) ONCE per block
        sC[0] = (float)tanh((double)pr[0]);
        sC[1] = (float)tanh((double)pr[1]);
        sC[2] = pr[2];
        sC[3] = pr[3];
    }
    __syncthreads();
    float w1 = sC[0], w2 = sC[1], w3 = sC[2], w4 = sC[3];
    float w4_2 = 2.0f * w4;

    // stage cc(t) = fmaf(w3, x*x, w1*x), coalesced: logical i <-> t = B-WUP+i
    for (int i = tid; i < XN; i += BLKA) {
        int t = B - WUP + i;
        float x = (t >= 0 && t < T) ? X[t] : 0.f;
        sCC[i] = fmaf(w3, x * x, w1 * x);
    }
    __syncthreads();

    int si = B + tid * CHA;
    // ---- phase 1: h chain into sZ ----
    if (si < nsteps) {
        int t0 = si - WUP; if (t0 < 0) t0 = 0;
        float h = 0.f;
        for (int t = t0; t < si; ++t) {
            float u = fmaf(w4, h, w2);
            h = fmaf(h, u, sCC[t - B + WUP]);
        }
        sZ[si - B] = h;                           // Z[si] (pre-step value)
        int e = si + CHA; if (e > nsteps) e = nsteps;
        for (int t = si; t < e; ++t) {
            float u = fmaf(w4, h, w2);
            h = fmaf(h, u, sCC[t - B + WUP]);
            sZ[t + 1 - B] = h;
        }
        if (tid == BLKA - 1) {                    // 31-step halo
            int he = e + 31; if (he > nsteps) he = nsteps;
            for (int t = e; t < he; ++t) {
                float u = fmaf(w4, h, w2);
                h = fmaf(h, u, sCC[t - B + WUP]);
                sZ[t + 1 - B] = h;
            }
        }
    }
    __syncthreads();

    // ---- coalesced Z writeout ----
    if (B == 0 && tid == 0) Z[0] = 0.f;
    for (int i = tid; i < TILE; i += BLKA) {
        int g = B + 1 + i;
        if (g <= nsteps) Z[g] = sZ[1 + i];
    }

    // ---- phase 2: box-screened anomaly scan ----
    // h in (HLO,HHI) => |a| in [C5BOX,C6BOX] subset (0,1) => window length == 6.
    float HHI, HLO;
    if (w4_2 > 0.f) { HHI = (C6BOX - w2) / w4_2; HLO = (C5BOX - w2) / w4_2; }
    else            { HHI = -1e30f; HLO = 1e30f; }   // box never passes -> exact
    if (si < nsteps) {
        int pe = si + CHA; if (pe > nsteps) pe = nsteps;
        int m = 0;
#pragma unroll
        for (int j = 0; j < 5; ++j) {
            float hv = sZ[si - B + j];
            m = (m >> 1) | ((hv > HLO && hv < HHI) ? 16 : 0);
        }
        for (int p = si; p < pe; ++p) {
            float hv = sZ[p - B + 5];
            m |= (hv > HLO && hv < HHI) ? 32 : 0;
            if (!(m == 63 && p + 6 <= nsteps)) {
                // exact (rare) path: replicate emit-loop decay recurrence
                float d = 1.f; int l = -1;
#pragma unroll 1
                for (int j = 0; j < 32; ++j) {
                    int t = p + j;
                    if (t >= nsteps) break;
                    float hh = sZ[t - B];
                    float a = __fadd_rn(w2, __fmul_rn(w4_2, hh));
                    d = __fmul_rn(d, fabsf(a));
                    if (d < THRESH) { l = j + 1; break; }
                }
                if (l != 6) {
                    int i = atomicAdd(&g_anom_n, 1);
                    if (i < MAXBP) { g_anom_p[i] = p; g_anom_l[i] = (l < 0) ? BIGL : l; }
                }
            }
            m >>= 1;
        }
    }
    __threadfence();
    __syncthreads();

    // ---- phase 3: last-finished block walks the reset orbit, exports consts ----
    if (tid == 0) {
        int tk = atomicAdd(&g_ticket, 1);
        if (tk == (int)gridDim.x - 1) {
            __threadfence();                      // acquire all blocks' writes
            int n = g_anom_n; if (n > MAXBP) n = MAXBP;
            for (int i = 1; i < n; ++i) {         // tiny insertion sort
                int p = g_anom_p[i], ll = g_anom_l[i], j = i - 1;
                while (j >= 0 && g_anom_p[j] > p) {
                    g_anom_p[j + 1] = g_anom_p[j]; g_anom_l[j + 1] = g_anom_l[j]; --j;
                }
                g_anom_p[j + 1] = p; g_anom_l[j + 1] = ll;
            }
            int pos = 0, K = 0;
            for (int i = 0; i < n && K < MAXBP; ++i) {
                int p = g_anom_p[i];
                if (p < pos) continue;
                if ((p - pos) % 6 != 0) continue; // not on the orbit
                int ll = g_anom_l[i];
                g_P[K] = p;
                if (ll >= BIGL) { g_Q[K] = 0x7fffffff; ++K; break; }
                g_Q[K] = p + ll; pos = p + ll; ++K;
            }
            g_K = K;
            g_anom_n = 0;                         // reset for next replay
            g_ticket = 0;
            // derived constants for k4
            g_C[0] = w2; g_C[1] = w4_2;
            g_C[2] = 1.f - w1 * w1;               // dt1
            g_C[3] = 1.f - w2 * w2;               // dt2
            g_C[4] = -2.f * w1 * (1.f - w1 * w1); // d2t1
            g_C[5] = -2.f * w2 * (1.f - w2 * w2); // d2t2
        }
    }
}

// window [ws, we] containing step s (we = reset step; emitted zeros there).
__device__ __forceinline__ void wse(int s, int& ws, int& we) {
    int K = g_K;
    if (K == 0 || s < g_P[0]) { ws = s - s % 6; we = ws + 5; return; }
    int lo = 0, hi = K - 1;
    while (lo < hi) {                             // last k with P[k] <= s
        int mid = (lo + hi + 1) >> 1;
        if (g_P[mid] <= s) lo = mid; else hi = mid - 1;
    }
    int q = g_Q[lo];
    if (s < q) { ws = g_P[lo]; we = q - 1; return; }
    int r = s - q;
    ws = q + (r - r % 6); we = ws + 5;
}

// ============================================================================
// k4: one step per thread, no reset logic (table-driven), direct wide stores.
// ============================================================================
__global__ __launch_bounds__(BLKB) void k4_main(const float* __restrict__ X,
                                                const float* __restrict__ Z,
                                                float* __restrict__ outJ,
                                                float* __restrict__ outH, int T) {
    __shared__ float sX4[BLKB + HALOB];
    __shared__ float sZ4[BLKB + HALOB];
    int nsteps = T - 1;
    int s0 = blockIdx.x * BLKB;
    int tid = threadIdx.x;

    if (blockIdx.x == 0 && tid == 0) {            // row 0 of J and H = 0
        ((float4*)outJ)[0] = make_float4(0, 0, 0, 0);
        float4 z4 = make_float4(0, 0, 0, 0);
        ((float4*)outH)[0] = z4; ((float4*)outH)[1] = z4;
        ((float4*)outH)[2] = z4; ((float4*)outH)[3] = z4;
    }

    for (int i = tid; i < BLKB + HALOB; i += BLKB) {   // stage X/Z coalesced
        int t = s0 - HALOB + i;
        float xv = 0.f, hv = 0.f;
        if (t >= 0 && t < nsteps) { xv = X[t]; hv = Z[t]; }
        sX4[i] = xv; sZ4[i] = hv;
    }
    __syncthreads();

    int s = s0 + tid;
    if (s >= nsteps) return;

    float w2   = g_C[0], w4_2 = g_C[1];
    float dt1  = g_C[2], dt2  = g_C[3];
    float d2t1 = g_C[4], d2t2 = g_C[5];

    int ws, we; wse(s, ws, we);
    float keep = (s == we) ? 0.f : 1.f;           // reset step emits zeros

    float J0 = 0, J1 = 0, J2 = 0, J3 = 0;
    float H00 = 0, H01 = 0, H02 = 0, H03 = 0, H11 = 0;
    float H12 = 0, H13 = 0, H22 = 0, H23 = 0, H33 = 0;

#pragma unroll 1
    for (int t = ws; t <= s; ++t) {               // no reset inside [ws, s]
        int li = t - s0 + HALOB;
        float x, h;
        if (li >= 0) { x = sX4[li]; h = sZ4[li]; }
        else         { x = X[t];    h = Z[t];   } // pathological far window
        float a  = __fadd_rn(w2, __fmul_rn(w4_2, h));
        float g3 = 2.f * h;
        H00 = fmaf(a, H00, x * d2t1);
        H01 = fmaf(a, H01, dt2 * J0);
        H02 = a * H02;
        H03 = fmaf(a, H03, g3 * J0);
        H11 = fmaf(a, H11, fmaf(2.f * dt2, J1, h * d2t2));
        H12 = fmaf(a, H12, dt2 * J2);
        H13 = fmaf(a, H13, fmaf(dt2, J3, g3 * J1));
        H22 = a * H22;
        H23 = fmaf(a, H23, g3 * J2);
        H33 = fmaf(a, H33, (2.f * g3) * J3);
        J0 = fmaf(a, J0, x * dt1);
        J1 = fmaf(a, J1, h * dt2);
        J2 = fmaf(a, J2, x * x);
        J3 = fmaf(a, J3, h * h);
    }

    J0 *= keep; J1 *= keep; J2 *= keep; J3 *= keep;
    H00 *= keep; H01 *= keep; H02 *= keep; H03 *= keep; H11 *= keep;
    H12 *= keep; H13 *= keep; H22 *= keep; H23 *= keep; H33 *= keep;

    ((float4*)outJ)[s + 1] = make_float4(J0, J1, J2, J3);
    float4* Hp = (float4*)outH + (size_t)(s + 1) * 4;
    Hp[0] = make_float4(H00, H01, H02, H03);
    Hp[1] = make_float4(H01, H11, H12, H13);
    Hp[2] = make_float4(H02, H12, H22, H23);
    Hp[3] = make_float4(H03, H13, H23, H33);
}

extern "C" void kernel_launch(void* const* d_in, const int* in_sizes, int n_in,
                              void* d_out, int out_size) {
    const float* X  = (const float*)d_in[0];
    const float* pr = (const float*)d_in[1];
    int T = in_sizes[0];
    float* out = (float*)d_out;
    float* Z = out;                        // [T]
    float* J = out + (size_t)T;            // [T,4]
    float* H = out + (size_t)5 * T;        // [T,4,4]

    int nsteps = T - 1;
    int gA = (nsteps + TILE - 1) / TILE;
    kA<<<gA, BLKA>>>(X, pr, Z, T);
    int gB = (nsteps + BLKB - 1) / BLKB;
    k4_main<<<gB, BLKB>>>(X, Z, J, H, T);
}

// round 6
// speedup vs baseline: 1.3996x; 1.3996x over previous
#include <cuda_runtime.h>
#include <math.h>

#define THRESH 1e-4f
#define MAXBP  8192
#define BIGL   0x40000000

// ---- kA config ----
#define BLKA 256
#define CHA  9                      // odd stride -> conflict-free smem chain reads
#define WUP  40
#define TILE (BLKA*CHA)             // 2304
#define XN   (TILE + WUP + 32)      // staged cc: t in [B-WUP, B+TILE+31]
#define SZN  (TILE + 32)
// static smem: (XN+SZN+4)*4 = 18,968 B  << 48 KB cap
// box-screen constants: TH^(1/6)*0.997 and TH^(1/5)*1.02
#define C6BOX 0.212742f
#define C5BOX 0.161659f

// ---- k4 config ----
#define BLKB  256
#define HALOB 8

// Scratch (no allocations); zero-init first run, self-reset for graph replays.
__device__ int g_anom_n = 0;
__device__ int g_ticket = 0;
__device__ int g_anom_p[MAXBP];
__device__ int g_anom_l[MAXBP];
__device__ int g_K;
__device__ int g_P[MAXBP];
__device__ int g_Q[MAXBP];
__device__ float g_C[8];            // w2, w4_2, dt1, dt2, d2t1, d2t2

// ============================================================================
// kA: fused Z-scan + box-screened anomaly scan + orbit walk (+ consts export).
// ============================================================================
__global__ __launch_bounds__(BLKA) void kA(const float* __restrict__ X,
                                           const float* __restrict__ pr,
                                           float* __restrict__ Z, int T) {
    __shared__ float sCC[XN];
    __shared__ float sZ[SZN];
    __shared__ float sC[4];
    int nsteps = T - 1;
    int B = blockIdx.x * TILE;
    int tid = threadIdx.x;

    if (tid == 0) {                 // tanh(double) ONCE per block
        sC[0] = (float)tanh((double)pr[0]);
        sC[1] = (float)tanh((double)pr[1]);
        sC[2] = pr[2];
        sC[3] = pr[3];
    }
    __syncthreads();
    float w1 = sC[0], w2 = sC[1], w3 = sC[2], w4 = sC[3];
    float w4_2 = 2.0f * w4;

    // stage cc(t) = fmaf(w3, x*x, w1*x), coalesced: logical i <-> t = B-WUP+i
    for (int i = tid; i < XN; i += BLKA) {
        int t = B - WUP + i;
        float x = (t >= 0 && t < T) ? X[t] : 0.f;
        sCC[i] = fmaf(w3, x * x, w1 * x);
    }
    __syncthreads();

    int si = B + tid * CHA;
    // ---- phase 1: h chain into sZ (warm-up converged) ----
    if (si < nsteps) {
        int t0 = si - WUP; if (t0 < 0) t0 = 0;
        float h = 0.f;
        for (int t = t0; t < si; ++t) {
            float u = fmaf(w4, h, w2);
            h = fmaf(h, u, sCC[t - B + WUP]);
        }
        sZ[si - B] = h;                           // Z[si] (pre-step value)
        int e = si + CHA; if (e > nsteps) e = nsteps;
        for (int t = si; t < e; ++t) {
            float u = fmaf(w4, h, w2);
            h = fmaf(h, u, sCC[t - B + WUP]);
            sZ[t + 1 - B] = h;
        }
        if (tid == BLKA - 1) {                    // 31-step halo
            int he = e + 31; if (he > nsteps) he = nsteps;
            for (int t = e; t < he; ++t) {
                float u = fmaf(w4, h, w2);
                h = fmaf(h, u, sCC[t - B + WUP]);
                sZ[t + 1 - B] = h;
            }
        }
    }
    __syncthreads();

    // ---- coalesced Z writeout ----
    if (B == 0 && tid == 0) Z[0] = 0.f;
    for (int i = tid; i < TILE; i += BLKA) {
        int g = B + 1 + i;
        if (g <= nsteps) Z[g] = sZ[1 + i];
    }

    // ---- phase 2: box-screened anomaly scan ----
    // h in (HLO,HHI) => |a| in [C5BOX,C6BOX] subset (0,1) => window length == 6.
    float HHI, HLO;
    if (w4_2 > 0.f) { HHI = (C6BOX - w2) / w4_2; HLO = (C5BOX - w2) / w4_2; }
    else            { HHI = -1e30f; HLO = 1e30f; }   // box never passes -> exact
    if (si < nsteps) {
        int pe = si + CHA; if (pe > nsteps) pe = nsteps;
        int m = 0;
#pragma unroll
        for (int j = 0; j < 5; ++j) {
            float hv = sZ[si - B + j];
            m = (m >> 1) | ((hv > HLO && hv < HHI) ? 16 : 0);
        }
        for (int p = si; p < pe; ++p) {
            float hv = sZ[p - B + 5];
            m |= (hv > HLO && hv < HHI) ? 32 : 0;
            if (!(m == 63 && p + 6 <= nsteps)) {
                // exact (rare) path: replicate emit-loop decay recurrence
                float d = 1.f; int l = -1;
#pragma unroll 1
                for (int j = 0; j < 32; ++j) {
                    int t = p + j;
                    if (t >= nsteps) break;
                    float hh = sZ[t - B];
                    float a = __fadd_rn(w2, __fmul_rn(w4_2, hh));
                    d = __fmul_rn(d, fabsf(a));
                    if (d < THRESH) { l = j + 1; break; }
                }
                if (l != 6) {
                    int i = atomicAdd(&g_anom_n, 1);
                    if (i < MAXBP) { g_anom_p[i] = p; g_anom_l[i] = (l < 0) ? BIGL : l; }
                }
            }
            m >>= 1;
        }
    }
    __threadfence();
    __syncthreads();

    // ---- phase 3: last-finished block walks the reset orbit, exports consts ----
    if (tid == 0) {
        int tk = atomicAdd(&g_ticket, 1);
        if (tk == (int)gridDim.x - 1) {
            __threadfence();
            int n = g_anom_n; if (n > MAXBP) n = MAXBP;
            for (int i = 1; i < n; ++i) {         // tiny insertion sort
                int p = g_anom_p[i], ll = g_anom_l[i], j = i - 1;
                while (j >= 0 && g_anom_p[j] > p) {
                    g_anom_p[j + 1] = g_anom_p[j]; g_anom_l[j + 1] = g_anom_l[j]; --j;
                }
                g_anom_p[j + 1] = p; g_anom_l[j + 1] = ll;
            }
            int pos = 0, K = 0;
            for (int i = 0; i < n && K < MAXBP; ++i) {
                int p = g_anom_p[i];
                if (p < pos) continue;
                if ((p - pos) % 6 != 0) continue; // not on the orbit
                int ll = g_anom_l[i];
                g_P[K] = p;
                if (ll >= BIGL) { g_Q[K] = 0x7fffffff; ++K; break; }
                g_Q[K] = p + ll; pos = p + ll; ++K;
            }
            g_K = K;
            g_anom_n = 0;                         // reset for next replay
            g_ticket = 0;
            g_C[0] = w2; g_C[1] = w4_2;
            g_C[2] = 1.f - w1 * w1;               // dt1
            g_C[3] = 1.f - w2 * w2;               // dt2
            g_C[4] = -2.f * w1 * (1.f - w1 * w1); // d2t1
            g_C[5] = -2.f * w2 * (1.f - w2 * w2); // d2t2
        }
    }
}

// window [ws, we] containing step s (we = reset step; emitted zeros there).
__device__ __forceinline__ void wse(int s, int& ws, int& we) {
    int K = g_K;
    if (K == 0 || s < g_P[0]) { ws = s - s % 6; we = ws + 5; return; }
    int lo = 0, hi = K - 1;
    while (lo < hi) {                             // last k with P[k] <= s
        int mid = (lo + hi + 1) >> 1;
        if (g_P[mid] <= s) lo = mid; else hi = mid - 1;
    }
    int q = g_Q[lo];
    if (s < q) { ws = g_P[lo]; we = q - 1; return; }
    int r = s - q;
    ws = q + (r - r % 6); we = ws + 5;
}

// one step of the J/H recurrence (a = w2 + w4_2*h must be precomputed)
#define JH_STEP(x, h, a)                                              \
    do {                                                              \
        float g3 = 2.f * (h);                                         \
        H00 = fmaf((a), H00, (x) * d2t1);                             \
        H01 = fmaf((a), H01, dt2 * J0);                               \
        H02 = (a) * H02;                                              \
        H03 = fmaf((a), H03, g3 * J0);                                \
        H11 = fmaf((a), H11, fmaf(2.f * dt2, J1, (h) * d2t2));        \
        H12 = fmaf((a), H12, dt2 * J2);                               \
        H13 = fmaf((a), H13, fmaf(dt2, J3, g3 * J1));                 \
        H22 = (a) * H22;                                              \
        H23 = fmaf((a), H23, g3 * J2);                                \
        H33 = fmaf((a), H33, (2.f * g3) * J3);                        \
        J0 = fmaf((a), J0, (x) * dt1);                                \
        J1 = fmaf((a), J1, (h) * dt2);                                \
        J2 = fmaf((a), J2, (x) * (x));                                \
        J3 = fmaf((a), J3, (h) * (h));                                \
    } while (0)

// ============================================================================
// k4: one step per thread; fixed 6-step unrolled masked rebuild; wide stores.
// ============================================================================
__global__ __launch_bounds__(BLKB) void k4_main(const float* __restrict__ X,
                                                const float* __restrict__ Z,
                                                float* __restrict__ outJ,
                                                float* __restrict__ outH, int T) {
    __shared__ float sX4[BLKB + HALOB];
    __shared__ float sZ4[BLKB + HALOB];
    int nsteps = T - 1;
    int s0 = blockIdx.x * BLKB;
    int tid = threadIdx.x;

    if (blockIdx.x == 0 && tid == 0) {            // row 0 of J and H = 0
        ((float4*)outJ)[0] = make_float4(0, 0, 0, 0);
        float4 z4 = make_float4(0, 0, 0, 0);
        ((float4*)outH)[0] = z4; ((float4*)outH)[1] = z4;
        ((float4*)outH)[2] = z4; ((float4*)outH)[3] = z4;
    }

    for (int i = tid; i < BLKB + HALOB; i += BLKB) {   // stage X/Z coalesced
        int t = s0 - HALOB + i;
        float xv = 0.f, hv = 0.f;
        if (t >= 0 && t < nsteps) { xv = X[t]; hv = Z[t]; }
        sX4[i] = xv; sZ4[i] = hv;
    }
    __syncthreads();

    int s = s0 + tid;
    if (s >= nsteps) return;

    float w2   = g_C[0], w4_2 = g_C[1];
    float dt1  = g_C[2], dt2  = g_C[3];
    float d2t1 = g_C[4], d2t2 = g_C[5];

    int ws, we; wse(s, ws, we);
    float keep = (s == we) ? 0.f : 1.f;           // reset step emits zeros

    float J0 = 0, J1 = 0, J2 = 0, J3 = 0;
    float H00 = 0, H01 = 0, H02 = 0, H03 = 0, H11 = 0;
    float H12 = 0, H13 = 0, H22 = 0, H23 = 0, H33 = 0;

    if (ws >= s - 5) {
        // hot path: exactly 6 straight-line steps t = s-5..s; steps with
        // t < ws are masked to identity (accumulators are 0, terms zeroed).
        int jmin = ws - (s - 5);                  // 0..5
#pragma unroll
        for (int j = 0; j < 6; ++j) {
            int li = tid + HALOB - 5 + j;         // always in-range (HALOB>=5)
            float msk = (j >= jmin) ? 1.f : 0.f;
            float x = sX4[li] * msk;
            float h = sZ4[li] * msk;
            float a = __fadd_rn(w2, __fmul_rn(w4_2, h));
            JH_STEP(x, h, a);
        }
    } else {
        // rare long window
#pragma unroll 1
        for (int t = ws; t <= s; ++t) {
            int li = t - s0 + HALOB;
            float x, h;
            if (li >= 0) { x = sX4[li]; h = sZ4[li]; }
            else         { x = X[t];    h = Z[t];   }
            float a = __fadd_rn(w2, __fmul_rn(w4_2, h));
            JH_STEP(x, h, a);
        }
    }

    J0 *= keep; J1 *= keep; J2 *= keep; J3 *= keep;
    H00 *= keep; H01 *= keep; H02 *= keep; H03 *= keep; H11 *= keep;
    H12 *= keep; H13 *= keep; H22 *= keep; H23 *= keep; H33 *= keep;

    ((float4*)outJ)[s + 1] = make_float4(J0, J1, J2, J3);
    float4* Hp = (float4*)outH + (size_t)(s + 1) * 4;
    Hp[0] = make_float4(H00, H01, H02, H03);
    Hp[1] = make_float4(H01, H11, H12, H13);
    Hp[2] = make_float4(H02, H12, H22, H23);
    Hp[3] = make_float4(H03, H13, H23, H33);
}

extern "C" void kernel_launch(void* const* d_in, const int* in_sizes, int n_in,
                              void* d_out, int out_size) {
    const float* X  = (const float*)d_in[0];
    const float* pr = (const float*)d_in[1];
    int T = in_sizes[0];
    float* out = (float*)d_out;
    float* Z = out;                        // [T]
    float* J = out + (size_t)T;            // [T,4]
    float* H = out + (size_t)5 * T;        // [T,4,4]

    int nsteps = T - 1;
    int gA = (nsteps + TILE - 1) / TILE;
    kA<<<gA, BLKA>>>(X, pr, Z, T);
    int gB = (nsteps + BLKB - 1) / BLKB;
    k4_main<<<gB, BLKB>>>(X, Z, J, H, T);
}

// round 7
// speedup vs baseline: 1.5016x; 1.0729x over previous
#include <cuda_runtime.h>
#include <math.h>

#define THRESH 1e-4f
#define MAXBP  8192
#define BIGL   0x40000000

// ---- kA config ----
#define BLKA 256
#define CHA  9                      // odd stride -> conflict-free smem chain reads
#define WUP  32
#define TILE (BLKA*CHA)             // 2304
#define XN   (TILE + WUP + 32)      // staged cc: t in [B-WUP, B+TILE+31]
#define SZN  (TILE + 32)
// box-screen constants: TH^(1/6)*0.997 and TH^(1/5)*1.02
#define C6BOX 0.212742f
#define C5BOX 0.161659f

// ---- k4 config ----
#define BLKB  256
#define HALOB 8
#define SLOT(i) ((i) ^ (((i) >> 3) & 7))   // float4-slot swizzle, conflict-free

// Scratch (no allocations); zero-init first run, self-reset for graph replays.
__device__ int g_anom_n = 0;
__device__ int g_ticket = 0;
__device__ int g_anom_p[MAXBP];
__device__ int g_anom_l[MAXBP];
__device__ int g_K;
__device__ int g_P[MAXBP];
__device__ int g_Q[MAXBP];
__device__ float g_C[8];            // w2, w4_2, dt1, dt2, d2t1, d2t2

// ============================================================================
// kA: fused Z-scan + box-screened anomaly scan + orbit walk (+ consts export).
// ============================================================================
__global__ __launch_bounds__(BLKA) void kA(const float* __restrict__ X,
                                           const float* __restrict__ pr,
                                           float* __restrict__ Z, int T) {
    __shared__ float sCC[XN];
    __shared__ float sZ[SZN];
    __shared__ float sC[4];
    int nsteps = T - 1;
    int B = blockIdx.x * TILE;
    int tid = threadIdx.x;

    if (tid == 0) {                 // tanh(double) ONCE per block
        sC[0] = (float)tanh((double)pr[0]);
        sC[1] = (float)tanh((double)pr[1]);
        sC[2] = pr[2];
        sC[3] = pr[3];
    }
    __syncthreads();
    float w1 = sC[0], w2 = sC[1], w3 = sC[2], w4 = sC[3];
    float w4_2 = 2.0f * w4;

    // stage cc(t) = fmaf(w3, x*x, w1*x), coalesced: logical i <-> t = B-WUP+i
    for (int i = tid; i < XN; i += BLKA) {
        int t = B - WUP + i;
        float x = (t >= 0 && t < T) ? X[t] : 0.f;
        sCC[i] = fmaf(w3, x * x, w1 * x);
    }
    __syncthreads();

    int si = B + tid * CHA;
    // ---- phase 1: h chain into sZ (warm-up converged) ----
    if (si < nsteps) {
        int t0 = si - WUP; if (t0 < 0) t0 = 0;
        float h = 0.f;
        for (int t = t0; t < si; ++t) {
            float u = fmaf(w4, h, w2);
            h = fmaf(h, u, sCC[t - B + WUP]);
        }
        sZ[si - B] = h;                           // Z[si] (pre-step value)
        int e = si + CHA; if (e > nsteps) e = nsteps;
        for (int t = si; t < e; ++t) {
            float u = fmaf(w4, h, w2);
            h = fmaf(h, u, sCC[t - B + WUP]);
            sZ[t + 1 - B] = h;
        }
        if (tid == BLKA - 1) {                    // 31-step halo
            int he = e + 31; if (he > nsteps) he = nsteps;
            for (int t = e; t < he; ++t) {
                float u = fmaf(w4, h, w2);
                h = fmaf(h, u, sCC[t - B + WUP]);
                sZ[t + 1 - B] = h;
            }
        }
    }
    __syncthreads();

    // ---- coalesced Z writeout ----
    if (B == 0 && tid == 0) Z[0] = 0.f;
    for (int i = tid; i < TILE; i += BLKA) {
        int g = B + 1 + i;
        if (g <= nsteps) Z[g] = sZ[1 + i];
    }

    // ---- phase 2: box-screened anomaly scan ----
    // h in (HLO,HHI) => |a| in [C5BOX,C6BOX] subset (0,1) => window length == 6.
    float HHI, HLO;
    if (w4_2 > 0.f) { HHI = (C6BOX - w2) / w4_2; HLO = (C5BOX - w2) / w4_2; }
    else            { HHI = -1e30f; HLO = 1e30f; }   // box never passes -> exact
    if (si < nsteps) {
        int pe = si + CHA; if (pe > nsteps) pe = nsteps;
        int m = 0;
#pragma unroll
        for (int j = 0; j < 5; ++j) {
            float hv = sZ[si - B + j];
            m = (m >> 1) | ((hv > HLO && hv < HHI) ? 16 : 0);
        }
        for (int p = si; p < pe; ++p) {
            float hv = sZ[p - B + 5];
            m |= (hv > HLO && hv < HHI) ? 32 : 0;
            if (!(m == 63 && p + 6 <= nsteps)) {
                // exact (rare) path: replicate emit-loop decay recurrence
                float d = 1.f; int l = -1;
#pragma unroll 1
                for (int j = 0; j < 32; ++j) {
                    int t = p + j;
                    if (t >= nsteps) break;
                    float hh = sZ[t - B];
                    float a = __fadd_rn(w2, __fmul_rn(w4_2, hh));
                    d = __fmul_rn(d, fabsf(a));
                    if (d < THRESH) { l = j + 1; break; }
                }
                if (l != 6) {
                    int i = atomicAdd(&g_anom_n, 1);
                    if (i < MAXBP) { g_anom_p[i] = p; g_anom_l[i] = (l < 0) ? BIGL : l; }
                }
            }
            m >>= 1;
        }
    }
    __threadfence();
    __syncthreads();

    // ---- phase 3: last-finished block walks the reset orbit, exports consts ----
    if (tid == 0) {
        int tk = atomicAdd(&g_ticket, 1);
        if (tk == (int)gridDim.x - 1) {
            __threadfence();
            int n = g_anom_n; if (n > MAXBP) n = MAXBP;
            for (int i = 1; i < n; ++i) {         // tiny insertion sort
                int p = g_anom_p[i], ll = g_anom_l[i], j = i - 1;
                while (j >= 0 && g_anom_p[j] > p) {
                    g_anom_p[j + 1] = g_anom_p[j]; g_anom_l[j + 1] = g_anom_l[j]; --j;
                }
                g_anom_p[j + 1] = p; g_anom_l[j + 1] = ll;
            }
            int pos = 0, K = 0;
            for (int i = 0; i < n && K < MAXBP; ++i) {
                int p = g_anom_p[i];
                if (p < pos) continue;
                if ((p - pos) % 6 != 0) continue; // not on the orbit
                int ll = g_anom_l[i];
                g_P[K] = p;
                if (ll >= BIGL) { g_Q[K] = 0x7fffffff; ++K; break; }
                g_Q[K] = p + ll; pos = p + ll; ++K;
            }
            g_K = K;
            g_anom_n = 0;                         // reset for next replay
            g_ticket = 0;
            g_C[0] = w2; g_C[1] = w4_2;
            g_C[2] = 1.f - w1 * w1;               // dt1
            g_C[3] = 1.f - w2 * w2;               // dt2
            g_C[4] = -2.f * w1 * (1.f - w1 * w1); // d2t1
            g_C[5] = -2.f * w2 * (1.f - w2 * w2); // d2t2
        }
    }
}

// window [ws, we] containing step s (we = reset step; emitted zeros there).
__device__ __forceinline__ void wse(int s, int& ws, int& we) {
    int K = g_K;
    if (K == 0 || s < g_P[0]) { ws = s - s % 6; we = ws + 5; return; }
    int lo = 0, hi = K - 1;
    while (lo < hi) {                             // last k with P[k] <= s
        int mid = (lo + hi + 1) >> 1;
        if (g_P[mid] <= s) lo = mid; else hi = mid - 1;
    }
    int q = g_Q[lo];
    if (s < q) { ws = g_P[lo]; we = q - 1; return; }
    int r = s - q;
    ws = q + (r - r % 6); we = ws + 5;
}

// one step of the J/H recurrence (a = w2 + w4_2*h must be precomputed)
#define JH_STEP(x, h, a)                                              \
    do {                                                              \
        float g3 = 2.f * (h);                                         \
        H00 = fmaf((a), H00, (x) * d2t1);                             \
        H01 = fmaf((a), H01, dt2 * J0);                               \
        H02 = (a) * H02;                                              \
        H03 = fmaf((a), H03, g3 * J0);                                \
        H11 = fmaf((a), H11, fmaf(2.f * dt2, J1, (h) * d2t2));        \
        H12 = fmaf((a), H12, dt2 * J2);                               \
        H13 = fmaf((a), H13, fmaf(dt2, J3, g3 * J1));                 \
        H22 = (a) * H22;                                              \
        H23 = fmaf((a), H23, g3 * J2);                                \
        H33 = fmaf((a), H33, (2.f * g3) * J3);                        \
        J0 = fmaf((a), J0, (x) * dt1);                                \
        J1 = fmaf((a), J1, (h) * dt2);                                \
        J2 = fmaf((a), J2, (x) * (x));                                \
        J3 = fmaf((a), J3, (h) * (h));                                \
    } while (0)

// ============================================================================
// k4: one step per thread; masked 6-step rebuild; H via swizzled smem ->
// fully coalesced float4 stream; J direct (already coalesced).
// ============================================================================
__global__ __launch_bounds__(BLKB) void k4_main(const float* __restrict__ X,
                                                const float* __restrict__ Z,
                                                float* __restrict__ outJ,
                                                float* __restrict__ outH, int T) {
    __shared__ float sX4[BLKB + HALOB];
    __shared__ float sZ4[BLKB + HALOB];
    __shared__ float4 sH4[BLKB * 4];              // 16 KB, swizzled slots
    int nsteps = T - 1;
    int s0 = blockIdx.x * BLKB;
    int tid = threadIdx.x;

    if (blockIdx.x == 0 && tid == 0) {            // row 0 of J and H = 0
        ((float4*)outJ)[0] = make_float4(0, 0, 0, 0);
        float4 z4 = make_float4(0, 0, 0, 0);
        ((float4*)outH)[0] = z4; ((float4*)outH)[1] = z4;
        ((float4*)outH)[2] = z4; ((float4*)outH)[3] = z4;
    }

    for (int i = tid; i < BLKB + HALOB; i += BLKB) {   // stage X/Z coalesced
        int t = s0 - HALOB + i;
        float xv = 0.f, hv = 0.f;
        if (t >= 0 && t < nsteps) { xv = X[t]; hv = Z[t]; }
        sX4[i] = xv; sZ4[i] = hv;
    }
    __syncthreads();

    int s = s0 + tid;
    if (s < nsteps) {
        float w2   = g_C[0], w4_2 = g_C[1];
        float dt1  = g_C[2], dt2  = g_C[3];
        float d2t1 = g_C[4], d2t2 = g_C[5];

        int ws, we; wse(s, ws, we);
        float keep = (s == we) ? 0.f : 1.f;       // reset step emits zeros

        float J0 = 0, J1 = 0, J2 = 0, J3 = 0;
        float H00 = 0, H01 = 0, H02 = 0, H03 = 0, H11 = 0;
        float H12 = 0, H13 = 0, H22 = 0, H23 = 0, H33 = 0;

        if (ws >= s - 5) {
            // hot path: exactly 6 straight-line steps t = s-5..s; steps with
            // t < ws masked to identity (accumulators 0, inputs zeroed).
            int jmin = ws - (s - 5);              // 0..5
#pragma unroll
            for (int j = 0; j < 6; ++j) {
                int li = tid + HALOB - 5 + j;     // always in-range (HALOB>=5)
                float msk = (j >= jmin) ? 1.f : 0.f;
                float x = sX4[li] * msk;
                float h = sZ4[li] * msk;
                float a = __fadd_rn(w2, __fmul_rn(w4_2, h));
                JH_STEP(x, h, a);
            }
        } else {
            // rare long window
#pragma unroll 1
            for (int t = ws; t <= s; ++t) {
                int li = t - s0 + HALOB;
                float x, h;
                if (li >= 0) { x = sX4[li]; h = sZ4[li]; }
                else         { x = X[t];    h = Z[t];   }
                float a = __fadd_rn(w2, __fmul_rn(w4_2, h));
                JH_STEP(x, h, a);
            }
        }

        J0 *= keep; J1 *= keep; J2 *= keep; J3 *= keep;
        H00 *= keep; H01 *= keep; H02 *= keep; H03 *= keep; H11 *= keep;
        H12 *= keep; H13 *= keep; H22 *= keep; H23 *= keep; H33 *= keep;

        ((float4*)outJ)[s + 1] = make_float4(J0, J1, J2, J3);
        int i0 = tid * 4;                          // stage H, swizzled
        sH4[SLOT(i0 + 0)] = make_float4(H00, H01, H02, H03);
        sH4[SLOT(i0 + 1)] = make_float4(H01, H11, H12, H13);
        sH4[SLOT(i0 + 2)] = make_float4(H02, H12, H22, H23);
        sH4[SLOT(i0 + 3)] = make_float4(H03, H13, H23, H33);
    }
    __syncthreads();

    int cnt = nsteps - s0; if (cnt > BLKB) cnt = BLKB;
    if (cnt < 0) cnt = 0;
    float4* Hout = (float4*)outH + (size_t)(s0 + 1) * 4;
#pragma unroll
    for (int k = 0; k < 4; ++k) {                 // coalesced H stream
        int i = tid + k * BLKB;
        if (i < cnt * 4) Hout[i] = sH4[SLOT(i)];
    }
}

extern "C" void kernel_launch(void* const* d_in, const int* in_sizes, int n_in,
                              void* d_out, int out_size) {
    const float* X  = (const float*)d_in[0];
    const float* pr = (const float*)d_in[1];
    int T = in_sizes[0];
    float* out = (float*)d_out;
    float* Z = out;                        // [T]
    float* J = out + (size_t)T;            // [T,4]
    float* H = out + (size_t)5 * T;        // [T,4,4]

    int nsteps = T - 1;
    int gA = (nsteps + TILE - 1) / TILE;
    kA<<<gA, BLKA>>>(X, pr, Z, T);
    int gB = (nsteps + BLKB - 1) / BLKB;
    k4_main<<<gB, BLKB>>>(X, Z, J, H, T);
}